// round 10
// baseline (speedup 1.0000x reference)
#include <cuda_runtime.h>
#include <cuda_fp16.h>
#include <mma.h>
#include <cstdint>

using namespace nvcuda;

#define N_NODES 100000
#define N_EDGES 1600000
#define D_IN    128
#define D_HID   128
#define D_OUT   70
#define D_OUT_P 72   // padded stride for layer-2 intermediates
#define NSCAN   ((N_NODES + 1023) / 1024)   // 98 scan blocks

// ---------------- scratch (static device memory; no allocation) -------------
__device__ __align__(256) int    g_deg   [N_NODES];
__device__ __align__(256) float  g_dinv  [N_NODES];
__device__ __align__(256) int    g_rowptr[N_NODES + 1];
__device__ __align__(256) int    g_cursor[N_NODES];
__device__ __align__(256) int    g_flag  [128];
__device__ __align__(256) int    g_pval  [128];
__device__ __align__(256) int    g_ival  [128];
__device__ __align__(256) int    g_nbr   [N_EDGES];
__device__ __align__(256) __half g_w1h   [128 * 128];   // W1 in fp16
__device__ __align__(256) __half g_w2h   [128 * 80];    // W2 in fp16, padded to 80
__device__ __align__(256) __half g_y1    [(size_t)N_NODES * D_HID];   // dinv-scaled x@W1
__device__ __align__(256) __half g_h     [(size_t)N_NODES * D_HID];
__device__ __align__(256) __half g_y2    [(size_t)N_NODES * D_OUT_P]; // dinv-scaled h@W2
__device__ int g_is64;

// ---------------- helpers ----------------------------------------------------
__device__ __forceinline__ int load_idx(const void* ei, long long i, int is64) {
    return is64 ? (int)(((const long long*)ei)[i]) : ((const int*)ei)[i];
}

__device__ __forceinline__ uint2 pack_half4(float x, float y, float z, float w) {
    __half2 h0 = __floats2half2_rn(x, y);
    __half2 h1 = __floats2half2_rn(z, w);
    uint2 u;
    u.x = *(unsigned*)&h0;
    u.y = *(unsigned*)&h1;
    return u;
}

__device__ __forceinline__ void add_half4(float4& a, unsigned lo_u, unsigned hi_u) {
    float2 lo = __half22float2(*(__half2*)&lo_u);
    float2 hi = __half22float2(*(__half2*)&hi_u);
    a.x += lo.x; a.y += lo.y; a.z += hi.x; a.w += hi.y;
}

// ---------------- weight pre-conversion (fp32 -> fp16, once per call) -------
__global__ void wcvt_k(const float* __restrict__ W1, const float* __restrict__ W2) {
    int i = blockIdx.x * blockDim.x + threadIdx.x;
    if (i < 128 * 128) g_w1h[i] = __float2half(W1[i]);
    if (i < 128 * 80) {
        int r = i / 80, n = i % 80;
        g_w2h[i] = __float2half((n < D_OUT) ? W2[(size_t)r * D_OUT + n] : 0.f);
    }
}

// ---------------- init: zero deg + scan flags, detect index width -----------
__global__ void init_k(const void* ei) {
    int i = blockIdx.x * blockDim.x + threadIdx.x;
    if (i < N_NODES) g_deg[i] = 0;
    if (i < 128) g_flag[i] = 0;
    if (i == 0) {
        const int* p = (const int*)ei;
        int is64 = 1;
        for (int t = 0; t < 1000; t++) {
            if (p[2 * t + 1] != 0) { is64 = 0; break; }
        }
        g_is64 = is64;
    }
}

__global__ void count_k(const void* __restrict__ ei) {
    int e = blockIdx.x * blockDim.x + threadIdx.x;
    if (e >= N_EDGES) return;
    int dst = load_idx(ei, (long long)N_EDGES + e, g_is64);
    atomicAdd(&g_deg[dst], 1);
}

// ---------------- fused scan (warp-shuffle + decoupled lookback) ------------
__global__ void __launch_bounds__(1024) scan_k() {
    __shared__ int warp_sums[32];
    __shared__ int s_off;
    int t = threadIdx.x, b = blockIdx.x;
    int lane = t & 31, wid = t >> 5;
    int i = b * 1024 + t;
    int deg = (i < N_NODES) ? g_deg[i] : 0;

    int v = deg;
    #pragma unroll
    for (int off = 1; off < 32; off <<= 1) {
        int n = __shfl_up_sync(0xffffffffu, v, off);
        if (lane >= off) v += n;
    }
    if (lane == 31) warp_sums[wid] = v;
    __syncthreads();

    if (wid == 0) {
        int wv = warp_sums[lane];
        #pragma unroll
        for (int off = 1; off < 32; off <<= 1) {
            int n = __shfl_up_sync(0xffffffffu, wv, off);
            if (lane >= off) wv += n;
        }
        warp_sums[lane] = wv;
        if (lane == 31) {
            int agg = wv;
            *(volatile int*)&g_pval[b] = agg;
            __threadfence();
            *(volatile int*)&g_flag[b] = 1;
            int off = 0;
            for (int p = b - 1; p >= 0; ) {
                int f;
                do { f = *(volatile int*)&g_flag[p]; } while (f == 0);
                __threadfence();
                if (f == 2) { off += *(volatile int*)&g_ival[p]; break; }
                off += *(volatile int*)&g_pval[p];
                p--;
            }
            *(volatile int*)&g_ival[b] = off + agg;
            __threadfence();
            *(volatile int*)&g_flag[b] = 2;
            s_off = off;
        }
    }
    __syncthreads();

    int incl = v + (wid ? warp_sums[wid - 1] : 0) + s_off;
    if (i < N_NODES) {
        g_rowptr[i + 1] = incl;
        g_cursor[i] = incl - deg;
        g_dinv[i] = rsqrtf((float)(deg + 1));   // +1 self-loop
    }
    if (i == 0) g_rowptr[0] = 0;
}

__global__ void fill_k(const void* __restrict__ ei) {
    int e = blockIdx.x * blockDim.x + threadIdx.x;
    if (e >= N_EDGES) return;
    int is64 = g_is64;
    int src = load_idx(ei, e, is64);
    int dst = load_idx(ei, (long long)N_EDGES + e, is64);
    int pos = atomicAdd(&g_cursor[dst], 1);
    g_nbr[pos] = src;
}

// ---------------- GEMM 1 (fp16 HMMA): y1 = dinv .* (x @ W1), 128x128 --------
#define LDAH 136   // half stride for A/W smem tiles
#define LDC  132   // float stride for epilogue smem
__global__ void __launch_bounds__(256) gemm1_k(const float* __restrict__ A) {
    extern __shared__ char smraw[];
    __half* sA = (__half*)smraw;            // 64 x LDAH
    __half* sW = sA + 64 * LDAH;            // 128 x LDAH
    float*  sC = (float*)smraw;             // 64 x LDC (epilogue alias)
    int tid = threadIdx.x;
    int wid = tid >> 5;
    int wm = wid & 1, wn = wid >> 1;        // 2 x 4 warp grid
    int r0 = blockIdx.x * 64;

    // A tile: 64x128 fp32 -> fp16 smem
    #pragma unroll
    for (int i = 0; i < 8; i++) {
        int l = tid + i * 256;
        int row = l >> 5, q = l & 31;
        float4 v = make_float4(0.f, 0.f, 0.f, 0.f);
        int gr = r0 + row;
        if (gr < N_NODES) v = *(const float4*)(A + (size_t)gr * 128 + q * 4);
        *(uint2*)(sA + row * LDAH + q * 4) = pack_half4(v.x, v.y, v.z, v.w);
    }
    // W: pre-converted fp16, raw 16B copies (2048 uint4)
    #pragma unroll
    for (int i = 0; i < 8; i++) {
        int l = tid + i * 256;
        int row = l >> 4, q = l & 15;
        *(uint4*)(sW + row * LDAH + q * 8) = *(const uint4*)(g_w1h + row * 128 + q * 8);
    }
    __syncthreads();

    wmma::fragment<wmma::accumulator, 16, 16, 16, float> acc[2][2];
    #pragma unroll
    for (int i = 0; i < 2; i++)
        #pragma unroll
        for (int j = 0; j < 2; j++)
            wmma::fill_fragment(acc[i][j], 0.f);

    #pragma unroll
    for (int k0 = 0; k0 < 128; k0 += 16) {
        wmma::fragment<wmma::matrix_a, 16, 16, 16, __half, wmma::row_major> af[2];
        wmma::fragment<wmma::matrix_b, 16, 16, 16, __half, wmma::row_major> bf[2];
        #pragma unroll
        for (int i = 0; i < 2; i++)
            wmma::load_matrix_sync(af[i], sA + (wm * 32 + i * 16) * LDAH + k0, LDAH);
        #pragma unroll
        for (int j = 0; j < 2; j++)
            wmma::load_matrix_sync(bf[j], sW + k0 * LDAH + wn * 32 + j * 16, LDAH);
        #pragma unroll
        for (int i = 0; i < 2; i++)
            #pragma unroll
            for (int j = 0; j < 2; j++)
                wmma::mma_sync(acc[i][j], af[i], bf[j], acc[i][j]);
    }

    __syncthreads();
    #pragma unroll
    for (int i = 0; i < 2; i++)
        #pragma unroll
        for (int j = 0; j < 2; j++)
            wmma::store_matrix_sync(sC + (wm * 32 + i * 16) * LDC + wn * 32 + j * 16,
                                    acc[i][j], LDC, wmma::mem_row_major);
    __syncthreads();
    #pragma unroll
    for (int i = 0; i < 8; i++) {
        int l = tid + i * 256;
        int row = l >> 5, q = l & 31;
        int gr = r0 + row;
        if (gr >= N_NODES) continue;
        float s = g_dinv[gr];
        float4 v = *(float4*)(sC + row * LDC + q * 4);
        *(uint2*)(g_y1 + (size_t)gr * 128 + q * 4) =
            pack_half4(v.x * s, v.y * s, v.z * s, v.w * s);
    }
}

// ---------------- GEMM 2 (fp16 HMMA): y2 = dinv .* (h @ W2), 128x70 ---------
#define LDW2H 88   // half stride for W2 smem
#define LDC2  84   // float stride for epilogue smem
__global__ void __launch_bounds__(320) gemm2_k() {
    extern __shared__ char smraw[];
    __half* sH = (__half*)smraw;            // 64 x LDAH
    __half* sW = sH + 64 * LDAH;            // 128 x LDW2H
    float*  sC = (float*)smraw;             // 64 x LDC2 (epilogue alias)
    int tid = threadIdx.x;
    int wid = tid >> 5;
    int wm = wid & 1, wn = wid >> 1;        // 2 x 5 warp grid
    int r0 = blockIdx.x * 64;

    for (int l = tid; l < 1024; l += 320) {
        int row = l >> 4, q = l & 15;
        int gr = r0 + row;
        uint4 u = make_uint4(0u, 0u, 0u, 0u);
        if (gr < N_NODES) u = *(const uint4*)(g_h + (size_t)gr * 128 + q * 8);
        *(uint4*)(sH + row * LDAH + q * 8) = u;
    }
    // W2: pre-converted fp16 (128 x 80), raw 16B copies
    for (int l = tid; l < 1280; l += 320) {
        int row = l / 10, q = l % 10;
        *(uint4*)(sW + row * LDW2H + q * 8) = *(const uint4*)(g_w2h + row * 80 + q * 8);
    }
    __syncthreads();

    wmma::fragment<wmma::accumulator, 16, 16, 16, float> acc[2];
    wmma::fill_fragment(acc[0], 0.f);
    wmma::fill_fragment(acc[1], 0.f);

    #pragma unroll
    for (int k0 = 0; k0 < 128; k0 += 16) {
        wmma::fragment<wmma::matrix_a, 16, 16, 16, __half, wmma::row_major> af[2];
        wmma::fragment<wmma::matrix_b, 16, 16, 16, __half, wmma::row_major> bf;
        wmma::load_matrix_sync(af[0], sH + (wm * 32) * LDAH + k0, LDAH);
        wmma::load_matrix_sync(af[1], sH + (wm * 32 + 16) * LDAH + k0, LDAH);
        wmma::load_matrix_sync(bf, sW + k0 * LDW2H + wn * 16, LDW2H);
        wmma::mma_sync(acc[0], af[0], bf, acc[0]);
        wmma::mma_sync(acc[1], af[1], bf, acc[1]);
    }

    __syncthreads();
    wmma::store_matrix_sync(sC + (wm * 32) * LDC2 + wn * 16, acc[0], LDC2, wmma::mem_row_major);
    wmma::store_matrix_sync(sC + (wm * 32 + 16) * LDC2 + wn * 16, acc[1], LDC2, wmma::mem_row_major);
    __syncthreads();
    for (int l = tid; l < 64 * 18; l += 320) {
        int row = l / 18, q = l % 18;
        int gr = r0 + row;
        if (gr >= N_NODES) continue;
        float s = g_dinv[gr];
        float4 v = *(float4*)(sC + row * LDC2 + q * 4);
        *(uint2*)(g_y2 + (size_t)gr * D_OUT_P + q * 4) =
            pack_half4(v.x * s, v.y * s, v.z * s, v.w * s);
    }
}

// ---------------- gather 1: h = relu(dinv .* (Σ_nbr y1 + y1_self) + b1) -----
// 1 warp/node, 2 edges per iteration: half-warp eh handles edge j+eh,
// lane owns 8 columns (one LDG.128); shfl_down(16) reduction at the end.
__global__ void __launch_bounds__(256) gather1_k(const float* __restrict__ b1) {
    int w = (blockIdx.x * 256 + threadIdx.x) >> 5;
    int lane = threadIdx.x & 31;
    if (w >= N_NODES) return;
    int hl = lane & 15, eh = lane >> 4;
    int start = g_rowptr[w], end = g_rowptr[w + 1];
    float4 a0 = make_float4(0.f, 0.f, 0.f, 0.f);
    float4 a1 = make_float4(0.f, 0.f, 0.f, 0.f);
    for (int base = start; base < end; base += 32) {
        int idx = base + lane;
        int s = (idx < end) ? g_nbr[idx] : -1;
        int cnt = min(32, end - base);
        for (int j = 0; j < cnt; j += 2) {
            int j1 = min(j + 1, cnt - 1);
            int sj0 = __shfl_sync(0xffffffffu, s, j);
            int sj1 = __shfl_sync(0xffffffffu, s, j1);
            int row = eh ? ((j + 1 < cnt) ? sj1 : -1) : sj0;
            if (row >= 0) {
                uint4 u = *(const uint4*)(g_y1 + (size_t)row * 128 + hl * 8);
                add_half4(a0, u.x, u.y);
                add_half4(a1, u.z, u.w);
            }
        }
    }
    // combine the two edge-halves
    a0.x += __shfl_down_sync(0xffffffffu, a0.x, 16);
    a0.y += __shfl_down_sync(0xffffffffu, a0.y, 16);
    a0.z += __shfl_down_sync(0xffffffffu, a0.z, 16);
    a0.w += __shfl_down_sync(0xffffffffu, a0.w, 16);
    a1.x += __shfl_down_sync(0xffffffffu, a1.x, 16);
    a1.y += __shfl_down_sync(0xffffffffu, a1.y, 16);
    a1.z += __shfl_down_sync(0xffffffffu, a1.z, 16);
    a1.w += __shfl_down_sync(0xffffffffu, a1.w, 16);
    if (eh == 0) {
        uint4 u = *(const uint4*)(g_y1 + (size_t)w * 128 + hl * 8);  // self loop
        add_half4(a0, u.x, u.y);
        add_half4(a1, u.z, u.w);
        float d = g_dinv[w];
        float4 bb0 = *(const float4*)(b1 + hl * 8);
        float4 bb1 = *(const float4*)(b1 + hl * 8 + 4);
        float h0 = fmaxf(0.f, fmaf(d, a0.x, bb0.x));
        float h1 = fmaxf(0.f, fmaf(d, a0.y, bb0.y));
        float h2 = fmaxf(0.f, fmaf(d, a0.z, bb0.z));
        float h3 = fmaxf(0.f, fmaf(d, a0.w, bb0.w));
        float h4 = fmaxf(0.f, fmaf(d, a1.x, bb1.x));
        float h5 = fmaxf(0.f, fmaf(d, a1.y, bb1.y));
        float h6 = fmaxf(0.f, fmaf(d, a1.z, bb1.z));
        float h7 = fmaxf(0.f, fmaf(d, a1.w, bb1.w));
        uint2 p0 = pack_half4(h0, h1, h2, h3);
        uint2 p1 = pack_half4(h4, h5, h6, h7);
        uint4 o = make_uint4(p0.x, p0.y, p1.x, p1.y);
        *(uint4*)(g_h + (size_t)w * 128 + hl * 8) = o;
    }
}

// ---------------- gather 2: out = dinv .* (Σ_nbr y2 + y2_self) + b2 ---------
// lanes hl<9 cover 72 padded cols (cols 70,71 are zero); 2 edges/iteration
__global__ void __launch_bounds__(256) gather2_k(const float* __restrict__ b2,
                                                 float* __restrict__ out) {
    int w = (blockIdx.x * 256 + threadIdx.x) >> 5;
    int lane = threadIdx.x & 31;
    if (w >= N_NODES) return;
    int hl = lane & 15, eh = lane >> 4;
    bool act = hl < 9;
    int start = g_rowptr[w], end = g_rowptr[w + 1];
    float4 a0 = make_float4(0.f, 0.f, 0.f, 0.f);
    float4 a1 = make_float4(0.f, 0.f, 0.f, 0.f);
    for (int base = start; base < end; base += 32) {
        int idx = base + lane;
        int s = (idx < end) ? g_nbr[idx] : -1;
        int cnt = min(32, end - base);
        for (int j = 0; j < cnt; j += 2) {
            int j1 = min(j + 1, cnt - 1);
            int sj0 = __shfl_sync(0xffffffffu, s, j);
            int sj1 = __shfl_sync(0xffffffffu, s, j1);
            int row = eh ? ((j + 1 < cnt) ? sj1 : -1) : sj0;
            if (row >= 0 && act) {
                uint4 u = *(const uint4*)(g_y2 + (size_t)row * D_OUT_P + hl * 8);
                add_half4(a0, u.x, u.y);
                add_half4(a1, u.z, u.w);
            }
        }
    }
    a0.x += __shfl_down_sync(0xffffffffu, a0.x, 16);
    a0.y += __shfl_down_sync(0xffffffffu, a0.y, 16);
    a0.z += __shfl_down_sync(0xffffffffu, a0.z, 16);
    a0.w += __shfl_down_sync(0xffffffffu, a0.w, 16);
    a1.x += __shfl_down_sync(0xffffffffu, a1.x, 16);
    a1.y += __shfl_down_sync(0xffffffffu, a1.y, 16);
    a1.z += __shfl_down_sync(0xffffffffu, a1.z, 16);
    a1.w += __shfl_down_sync(0xffffffffu, a1.w, 16);
    if (eh == 0 && act) {
        uint4 u = *(const uint4*)(g_y2 + (size_t)w * D_OUT_P + hl * 8);  // self
        add_half4(a0, u.x, u.y);
        add_half4(a1, u.z, u.w);
        float d = g_dinv[w];
        int c = hl * 8;
        float2* o2 = (float2*)(out + (size_t)w * D_OUT + c);
        if (hl < 8) {
            o2[0] = make_float2(fmaf(d, a0.x, b2[c + 0]), fmaf(d, a0.y, b2[c + 1]));
            o2[1] = make_float2(fmaf(d, a0.z, b2[c + 2]), fmaf(d, a0.w, b2[c + 3]));
            o2[2] = make_float2(fmaf(d, a1.x, b2[c + 4]), fmaf(d, a1.y, b2[c + 5]));
            o2[3] = make_float2(fmaf(d, a1.z, b2[c + 6]), fmaf(d, a1.w, b2[c + 7]));
        } else {   // hl == 8: cols 64..69 only
            o2[0] = make_float2(fmaf(d, a0.x, b2[64]), fmaf(d, a0.y, b2[65]));
            o2[1] = make_float2(fmaf(d, a0.z, b2[66]), fmaf(d, a0.w, b2[67]));
            o2[2] = make_float2(fmaf(d, a1.x, b2[68]), fmaf(d, a1.y, b2[69]));
        }
    }
}

// ---------------- launch -----------------------------------------------------
extern "C" void kernel_launch(void* const* d_in, const int* in_sizes, int n_in,
                              void* d_out, int out_size) {
    const float* x  = (const float*)d_in[0];
    const void*  ei = d_in[1];
    const float* W1 = (const float*)d_in[2];
    const float* b1 = (const float*)d_in[3];
    const float* W2 = (const float*)d_in[4];
    const float* b2 = (const float*)d_in[5];
    float* out = (float*)d_out;

    const int smem1 = (64 * LDAH + 128 * LDAH) * 2 > 64 * LDC * 4
                    ? (64 * LDAH + 128 * LDAH) * 2 : 64 * LDC * 4;     // 52224
    const int smem2 = (64 * LDAH + 128 * LDW2H) * 2 > 64 * LDC2 * 4
                    ? (64 * LDAH + 128 * LDW2H) * 2 : 64 * LDC2 * 4;   // 39936

    static cudaStream_t s2 = nullptr;
    static cudaEvent_t ev0 = nullptr, ev_fork = nullptr, ev_join = nullptr;
    if (!s2) {
        cudaStreamCreateWithFlags(&s2, cudaStreamNonBlocking);
        cudaEventCreateWithFlags(&ev0, cudaEventDisableTiming);
        cudaEventCreateWithFlags(&ev_fork, cudaEventDisableTiming);
        cudaEventCreateWithFlags(&ev_join, cudaEventDisableTiming);
        cudaFuncSetAttribute(gemm1_k, cudaFuncAttributeMaxDynamicSharedMemorySize, smem1);
        cudaFuncSetAttribute(gemm2_k, cudaFuncAttributeMaxDynamicSharedMemorySize, smem2);
    }

    // fork for weight conversion (no deps; overlaps the CSR chain)
    cudaEventRecord(ev0, 0);
    cudaStreamWaitEvent(s2, ev0, 0);
    wcvt_k<<<64, 256, 0, s2>>>(W1, W2);

    init_k<<<(N_NODES + 255) / 256, 256>>>(ei);
    count_k<<<(N_EDGES + 255) / 256, 256>>>(ei);
    scan_k<<<NSCAN, 1024>>>();

    // fork: gemm1 (needs dinv from scan + fp16 W1) runs concurrent with fill
    cudaEventRecord(ev_fork, 0);
    cudaStreamWaitEvent(s2, ev_fork, 0);
    gemm1_k<<<(N_NODES + 63) / 64, 256, smem1, s2>>>(x);
    fill_k<<<(N_EDGES + 255) / 256, 256>>>(ei);
    cudaEventRecord(ev_join, s2);
    cudaStreamWaitEvent(0, ev_join, 0);

    gather1_k<<<(N_NODES * 32 + 255) / 256, 256>>>(b1);
    gemm2_k<<<(N_NODES + 63) / 64, 320, smem2>>>();
    gather2_k<<<(N_NODES * 32 + 255) / 256, 256>>>(b2, out);
}

// round 11
// speedup vs baseline: 1.0881x; 1.0881x over previous
#include <cuda_runtime.h>
#include <cuda_fp16.h>
#include <mma.h>
#include <cstdint>

using namespace nvcuda;

#define N_NODES 100000
#define N_EDGES 1600000
#define D_IN    128
#define D_HID   128
#define D_OUT   70
#define D_OUT_P 72   // padded stride for layer-2 intermediates
#define NSCAN   ((N_NODES + 1023) / 1024)   // 98 scan blocks

// ---------------- scratch (static device memory; no allocation) -------------
__device__ __align__(256) int    g_deg   [N_NODES];
__device__ __align__(256) float  g_dinv  [N_NODES];
__device__ __align__(256) int    g_rowptr[N_NODES + 1];
__device__ __align__(256) int    g_cursor[N_NODES];
__device__ __align__(256) int    g_flag  [128];
__device__ __align__(256) int    g_pval  [128];
__device__ __align__(256) int    g_ival  [128];
__device__ __align__(256) int    g_nbr   [N_EDGES];
__device__ __align__(256) __half g_w1h   [128 * 128];   // W1 in fp16
__device__ __align__(256) __half g_w2h   [128 * 80];    // W2 in fp16, padded to 80
__device__ __align__(256) __half g_y1    [(size_t)N_NODES * D_HID];   // dinv-scaled x@W1
__device__ __align__(256) __half g_h     [(size_t)N_NODES * D_HID];
__device__ __align__(256) __half g_y2    [(size_t)N_NODES * D_OUT_P]; // dinv-scaled h@W2
__device__ int g_is64;

// ---------------- helpers ----------------------------------------------------
__device__ __forceinline__ int load_idx(const void* ei, long long i, int is64) {
    return is64 ? (int)(((const long long*)ei)[i]) : ((const int*)ei)[i];
}

__device__ __forceinline__ uint2 pack_half4(float x, float y, float z, float w) {
    __half2 h0 = __floats2half2_rn(x, y);
    __half2 h1 = __floats2half2_rn(z, w);
    uint2 u;
    u.x = *(unsigned*)&h0;
    u.y = *(unsigned*)&h1;
    return u;
}

__device__ __forceinline__ void add_half4(float4& a, uint2 u) {
    float2 lo = __half22float2(*(__half2*)&u.x);
    float2 hi = __half22float2(*(__half2*)&u.y);
    a.x += lo.x; a.y += lo.y; a.z += hi.x; a.w += hi.y;
}

// ---------------- weight pre-conversion (fp32 -> fp16, once per call) -------
__global__ void wcvt_k(const float* __restrict__ W1, const float* __restrict__ W2) {
    int i = blockIdx.x * blockDim.x + threadIdx.x;
    if (i < 128 * 128) g_w1h[i] = __float2half(W1[i]);
    if (i < 128 * 80) {
        int r = i / 80, n = i % 80;
        g_w2h[i] = __float2half((n < D_OUT) ? W2[(size_t)r * D_OUT + n] : 0.f);
    }
}

// ---------------- init: zero deg + scan flags, detect index width -----------
__global__ void init_k(const void* ei) {
    int i = blockIdx.x * blockDim.x + threadIdx.x;
    if (i < N_NODES) g_deg[i] = 0;
    if (i < 128) g_flag[i] = 0;
    if (i == 0) {
        const int* p = (const int*)ei;
        int is64 = 1;
        for (int t = 0; t < 1000; t++) {
            if (p[2 * t + 1] != 0) { is64 = 0; break; }
        }
        g_is64 = is64;
    }
}

__global__ void count_k(const void* __restrict__ ei) {
    int e = blockIdx.x * blockDim.x + threadIdx.x;
    if (e >= N_EDGES) return;
    int dst = load_idx(ei, (long long)N_EDGES + e, g_is64);
    atomicAdd(&g_deg[dst], 1);
}

// ---------------- fused scan (warp-shuffle + decoupled lookback) ------------
__global__ void __launch_bounds__(1024) scan_k() {
    __shared__ int warp_sums[32];
    __shared__ int s_off;
    int t = threadIdx.x, b = blockIdx.x;
    int lane = t & 31, wid = t >> 5;
    int i = b * 1024 + t;
    int deg = (i < N_NODES) ? g_deg[i] : 0;

    int v = deg;
    #pragma unroll
    for (int off = 1; off < 32; off <<= 1) {
        int n = __shfl_up_sync(0xffffffffu, v, off);
        if (lane >= off) v += n;
    }
    if (lane == 31) warp_sums[wid] = v;
    __syncthreads();

    if (wid == 0) {
        int wv = warp_sums[lane];
        #pragma unroll
        for (int off = 1; off < 32; off <<= 1) {
            int n = __shfl_up_sync(0xffffffffu, wv, off);
            if (lane >= off) wv += n;
        }
        warp_sums[lane] = wv;
        if (lane == 31) {
            int agg = wv;
            *(volatile int*)&g_pval[b] = agg;
            __threadfence();
            *(volatile int*)&g_flag[b] = 1;
            int off = 0;
            for (int p = b - 1; p >= 0; ) {
                int f;
                do { f = *(volatile int*)&g_flag[p]; } while (f == 0);
                __threadfence();
                if (f == 2) { off += *(volatile int*)&g_ival[p]; break; }
                off += *(volatile int*)&g_pval[p];
                p--;
            }
            *(volatile int*)&g_ival[b] = off + agg;
            __threadfence();
            *(volatile int*)&g_flag[b] = 2;
            s_off = off;
        }
    }
    __syncthreads();

    int incl = v + (wid ? warp_sums[wid - 1] : 0) + s_off;
    if (i < N_NODES) {
        g_rowptr[i + 1] = incl;
        g_cursor[i] = incl - deg;
        g_dinv[i] = rsqrtf((float)(deg + 1));   // +1 self-loop
    }
    if (i == 0) g_rowptr[0] = 0;
}

__global__ void fill_k(const void* __restrict__ ei) {
    int e = blockIdx.x * blockDim.x + threadIdx.x;
    if (e >= N_EDGES) return;
    int is64 = g_is64;
    int src = load_idx(ei, e, is64);
    int dst = load_idx(ei, (long long)N_EDGES + e, is64);
    int pos = atomicAdd(&g_cursor[dst], 1);
    g_nbr[pos] = src;
}

// ---------------- GEMM 1 (fp16 HMMA): y1 = dinv .* (x @ W1), 128x128 --------
#define LDAH 136   // half stride for A/W smem tiles
#define LDC  132   // float stride for epilogue smem
__global__ void __launch_bounds__(256) gemm1_k(const float* __restrict__ A) {
    extern __shared__ char smraw[];
    __half* sA = (__half*)smraw;            // 64 x LDAH
    __half* sW = sA + 64 * LDAH;            // 128 x LDAH
    float*  sC = (float*)smraw;             // 64 x LDC (epilogue alias)
    int tid = threadIdx.x;
    int wid = tid >> 5;
    int wm = wid & 1, wn = wid >> 1;        // 2 x 4 warp grid
    int r0 = blockIdx.x * 64;

    // A tile: 64x128 fp32 -> fp16 smem
    #pragma unroll
    for (int i = 0; i < 8; i++) {
        int l = tid + i * 256;
        int row = l >> 5, q = l & 31;
        float4 v = make_float4(0.f, 0.f, 0.f, 0.f);
        int gr = r0 + row;
        if (gr < N_NODES) v = *(const float4*)(A + (size_t)gr * 128 + q * 4);
        *(uint2*)(sA + row * LDAH + q * 4) = pack_half4(v.x, v.y, v.z, v.w);
    }
    // W: pre-converted fp16, raw 16B copies (2048 uint4)
    #pragma unroll
    for (int i = 0; i < 8; i++) {
        int l = tid + i * 256;
        int row = l >> 4, q = l & 15;
        *(uint4*)(sW + row * LDAH + q * 8) = *(const uint4*)(g_w1h + row * 128 + q * 8);
    }
    __syncthreads();

    wmma::fragment<wmma::accumulator, 16, 16, 16, float> acc[2][2];
    #pragma unroll
    for (int i = 0; i < 2; i++)
        #pragma unroll
        for (int j = 0; j < 2; j++)
            wmma::fill_fragment(acc[i][j], 0.f);

    #pragma unroll
    for (int k0 = 0; k0 < 128; k0 += 16) {
        wmma::fragment<wmma::matrix_a, 16, 16, 16, __half, wmma::row_major> af[2];
        wmma::fragment<wmma::matrix_b, 16, 16, 16, __half, wmma::row_major> bf[2];
        #pragma unroll
        for (int i = 0; i < 2; i++)
            wmma::load_matrix_sync(af[i], sA + (wm * 32 + i * 16) * LDAH + k0, LDAH);
        #pragma unroll
        for (int j = 0; j < 2; j++)
            wmma::load_matrix_sync(bf[j], sW + k0 * LDAH + wn * 32 + j * 16, LDAH);
        #pragma unroll
        for (int i = 0; i < 2; i++)
            #pragma unroll
            for (int j = 0; j < 2; j++)
                wmma::mma_sync(acc[i][j], af[i], bf[j], acc[i][j]);
    }

    __syncthreads();
    #pragma unroll
    for (int i = 0; i < 2; i++)
        #pragma unroll
        for (int j = 0; j < 2; j++)
            wmma::store_matrix_sync(sC + (wm * 32 + i * 16) * LDC + wn * 32 + j * 16,
                                    acc[i][j], LDC, wmma::mem_row_major);
    __syncthreads();
    #pragma unroll
    for (int i = 0; i < 8; i++) {
        int l = tid + i * 256;
        int row = l >> 5, q = l & 31;
        int gr = r0 + row;
        if (gr >= N_NODES) continue;
        float s = g_dinv[gr];
        float4 v = *(float4*)(sC + row * LDC + q * 4);
        *(uint2*)(g_y1 + (size_t)gr * 128 + q * 4) =
            pack_half4(v.x * s, v.y * s, v.z * s, v.w * s);
    }
}

// ---------------- GEMM 2 (fp16 HMMA): y2 = dinv .* (h @ W2), 128x70 ---------
#define LDW2H 88   // half stride for W2 smem
#define LDC2  84   // float stride for epilogue smem
__global__ void __launch_bounds__(320) gemm2_k() {
    extern __shared__ char smraw[];
    __half* sH = (__half*)smraw;            // 64 x LDAH
    __half* sW = sH + 64 * LDAH;            // 128 x LDW2H
    float*  sC = (float*)smraw;             // 64 x LDC2 (epilogue alias)
    int tid = threadIdx.x;
    int wid = tid >> 5;
    int wm = wid & 1, wn = wid >> 1;        // 2 x 5 warp grid
    int r0 = blockIdx.x * 64;

    for (int l = tid; l < 1024; l += 320) {
        int row = l >> 4, q = l & 15;
        int gr = r0 + row;
        uint4 u = make_uint4(0u, 0u, 0u, 0u);
        if (gr < N_NODES) u = *(const uint4*)(g_h + (size_t)gr * 128 + q * 8);
        *(uint4*)(sH + row * LDAH + q * 8) = u;
    }
    // W2: pre-converted fp16 (128 x 80), raw 16B copies
    for (int l = tid; l < 1280; l += 320) {
        int row = l / 10, q = l % 10;
        *(uint4*)(sW + row * LDW2H + q * 8) = *(const uint4*)(g_w2h + row * 80 + q * 8);
    }
    __syncthreads();

    wmma::fragment<wmma::accumulator, 16, 16, 16, float> acc[2];
    wmma::fill_fragment(acc[0], 0.f);
    wmma::fill_fragment(acc[1], 0.f);

    #pragma unroll
    for (int k0 = 0; k0 < 128; k0 += 16) {
        wmma::fragment<wmma::matrix_a, 16, 16, 16, __half, wmma::row_major> af[2];
        wmma::fragment<wmma::matrix_b, 16, 16, 16, __half, wmma::row_major> bf;
        wmma::load_matrix_sync(af[0], sH + (wm * 32) * LDAH + k0, LDAH);
        wmma::load_matrix_sync(af[1], sH + (wm * 32 + 16) * LDAH + k0, LDAH);
        wmma::load_matrix_sync(bf, sW + k0 * LDW2H + wn * 16, LDW2H);
        wmma::mma_sync(acc[0], af[0], bf, acc[0]);
        wmma::mma_sync(acc[1], af[1], bf, acc[1]);
    }

    __syncthreads();
    wmma::store_matrix_sync(sC + (wm * 32) * LDC2 + wn * 16, acc[0], LDC2, wmma::mem_row_major);
    wmma::store_matrix_sync(sC + (wm * 32 + 16) * LDC2 + wn * 16, acc[1], LDC2, wmma::mem_row_major);
    __syncthreads();
    for (int l = tid; l < 64 * 18; l += 320) {
        int row = l / 18, q = l % 18;
        int gr = r0 + row;
        if (gr >= N_NODES) continue;
        float s = g_dinv[gr];
        float4 v = *(float4*)(sC + row * LDC2 + q * 4);
        *(uint2*)(g_y2 + (size_t)gr * D_OUT_P + q * 4) =
            pack_half4(v.x * s, v.y * s, v.z * s, v.w * s);
    }
}

// ---------------- gather 1: h = relu(dinv .* (Σ_nbr y1 + y1_self) + b1) -----
// one warp per node; lane l owns columns [4l, 4l+4); shfl index broadcast
__global__ void __launch_bounds__(256) gather1_k(const float* __restrict__ b1) {
    int w = (blockIdx.x * 256 + threadIdx.x) >> 5;
    int lane = threadIdx.x & 31;
    if (w >= N_NODES) return;
    int start = g_rowptr[w], end = g_rowptr[w + 1];
    float4 a = make_float4(0.f, 0.f, 0.f, 0.f);
    add_half4(a, *(const uint2*)(g_y1 + (size_t)w * 128 + lane * 4));  // self
    for (int base = start; base < end; base += 32) {
        int idx = base + lane;
        int s = (idx < end) ? g_nbr[idx] : 0;
        int cnt = min(32, end - base);
        for (int j = 0; j < cnt; j++) {
            int sj = __shfl_sync(0xffffffffu, s, j);
            add_half4(a, *(const uint2*)(g_y1 + (size_t)sj * 128 + lane * 4));
        }
    }
    float d = g_dinv[w];
    float4 bb = *(const float4*)(b1 + lane * 4);
    float hx = fmaxf(0.f, fmaf(d, a.x, bb.x));
    float hy = fmaxf(0.f, fmaf(d, a.y, bb.y));
    float hz = fmaxf(0.f, fmaf(d, a.z, bb.z));
    float hw = fmaxf(0.f, fmaf(d, a.w, bb.w));
    *(uint2*)(g_h + (size_t)w * 128 + lane * 4) = pack_half4(hx, hy, hz, hw);
}

// ---------------- gather 2: out = dinv .* (Σ_nbr y2 + y2_self) + b2 ---------
__global__ void __launch_bounds__(256) gather2_k(const float* __restrict__ b2,
                                                 float* __restrict__ out) {
    int w = (blockIdx.x * 256 + threadIdx.x) >> 5;
    int lane = threadIdx.x & 31;
    if (w >= N_NODES) return;
    int start = g_rowptr[w], end = g_rowptr[w + 1];
    float4 a = make_float4(0.f, 0.f, 0.f, 0.f);
    bool act = lane < 18;
    size_t co = (size_t)lane * 4;
    if (act) add_half4(a, *(const uint2*)(g_y2 + (size_t)w * D_OUT_P + co));
    for (int base = start; base < end; base += 32) {
        int idx = base + lane;
        int s = (idx < end) ? g_nbr[idx] : 0;
        int cnt = min(32, end - base);
        for (int j = 0; j < cnt; j++) {
            int sj = __shfl_sync(0xffffffffu, s, j);
            if (act) add_half4(a, *(const uint2*)(g_y2 + (size_t)sj * D_OUT_P + co));
        }
    }
    if (act) {
        float d = g_dinv[w];
        int c = lane * 4;
        float* o = out + (size_t)w * D_OUT + c;
        float2 r0 = make_float2(fmaf(d, a.x, b2[c]), fmaf(d, a.y, b2[c + 1]));
        *(float2*)o = r0;
        if (lane < 17) {
            float2 r1 = make_float2(fmaf(d, a.z, b2[c + 2]), fmaf(d, a.w, b2[c + 3]));
            *(float2*)(o + 2) = r1;
        }
    }
}

// ---------------- launch -----------------------------------------------------
extern "C" void kernel_launch(void* const* d_in, const int* in_sizes, int n_in,
                              void* d_out, int out_size) {
    const float* x  = (const float*)d_in[0];
    const void*  ei = d_in[1];
    const float* W1 = (const float*)d_in[2];
    const float* b1 = (const float*)d_in[3];
    const float* W2 = (const float*)d_in[4];
    const float* b2 = (const float*)d_in[5];
    float* out = (float*)d_out;

    const int smem1 = (64 * LDAH + 128 * LDAH) * 2 > 64 * LDC * 4
                    ? (64 * LDAH + 128 * LDAH) * 2 : 64 * LDC * 4;     // 52224
    const int smem2 = (64 * LDAH + 128 * LDW2H) * 2 > 64 * LDC2 * 4
                    ? (64 * LDAH + 128 * LDW2H) * 2 : 64 * LDC2 * 4;   // 39936

    static cudaStream_t s2 = nullptr;
    static cudaEvent_t ev0 = nullptr, ev_fork = nullptr, ev_join = nullptr;
    if (!s2) {
        cudaStreamCreateWithFlags(&s2, cudaStreamNonBlocking);
        cudaEventCreateWithFlags(&ev0, cudaEventDisableTiming);
        cudaEventCreateWithFlags(&ev_fork, cudaEventDisableTiming);
        cudaEventCreateWithFlags(&ev_join, cudaEventDisableTiming);
        cudaFuncSetAttribute(gemm1_k, cudaFuncAttributeMaxDynamicSharedMemorySize, smem1);
        cudaFuncSetAttribute(gemm2_k, cudaFuncAttributeMaxDynamicSharedMemorySize, smem2);
    }

    // fork for weight conversion (no deps; overlaps the CSR chain)
    cudaEventRecord(ev0, 0);
    cudaStreamWaitEvent(s2, ev0, 0);
    wcvt_k<<<64, 256, 0, s2>>>(W1, W2);

    init_k<<<(N_NODES + 255) / 256, 256>>>(ei);
    count_k<<<(N_EDGES + 255) / 256, 256>>>(ei);
    scan_k<<<NSCAN, 1024>>>();

    // fork: gemm1 (needs dinv from scan + fp16 W1) runs concurrent with fill
    cudaEventRecord(ev_fork, 0);
    cudaStreamWaitEvent(s2, ev_fork, 0);
    gemm1_k<<<(N_NODES + 63) / 64, 256, smem1, s2>>>(x);
    fill_k<<<(N_EDGES + 255) / 256, 256>>>(ei);
    cudaEventRecord(ev_join, s2);
    cudaStreamWaitEvent(0, ev_join, 0);

    gather1_k<<<(N_NODES * 32 + 255) / 256, 256>>>(b1);
    gemm2_k<<<(N_NODES + 63) / 64, 320, smem2>>>();
    gather2_k<<<(N_NODES * 32 + 255) / 256, 256>>>(b2, out);
}

// round 12
// speedup vs baseline: 1.1510x; 1.0578x over previous
#include <cuda_runtime.h>
#include <cuda_fp16.h>
#include <mma.h>
#include <cstdint>

using namespace nvcuda;

#define N_NODES 100000
#define N_EDGES 1600000
#define D_IN    128
#define D_HID   128
#define D_OUT   70
#define D_OUT_P 72   // padded stride for layer-2 intermediates
#define NSCAN   ((N_NODES + 1023) / 1024)   // 98 scan blocks

// ---------------- scratch (static device memory; no allocation) -------------
__device__ __align__(256) int    g_deg   [N_NODES];
__device__ __align__(256) float  g_dinv  [N_NODES];
__device__ __align__(256) int    g_rowptr[N_NODES + 1];
__device__ __align__(256) int    g_cursor[N_NODES];
__device__ __align__(256) int    g_flag  [128];
__device__ __align__(256) int    g_pval  [128];
__device__ __align__(256) int    g_ival  [128];
__device__ __align__(256) int    g_nbr   [N_EDGES];
__device__ __align__(256) __half g_w1h   [128 * 128];   // W1 in fp16
__device__ __align__(256) __half g_w2h   [128 * 80];    // W2 in fp16, padded to 80
__device__ __align__(256) __half g_y1    [(size_t)N_NODES * D_HID];   // dinv-scaled x@W1
__device__ __align__(256) __half g_h     [(size_t)N_NODES * D_HID];
__device__ __align__(256) __half g_y2    [(size_t)N_NODES * D_OUT_P]; // dinv-scaled h@W2
__device__ int g_is64;

// ---------------- helpers ----------------------------------------------------
__device__ __forceinline__ int load_idx(const void* ei, long long i, int is64) {
    return is64 ? (int)(((const long long*)ei)[i]) : ((const int*)ei)[i];
}

__device__ __forceinline__ uint2 pack_half4(float x, float y, float z, float w) {
    __half2 h0 = __floats2half2_rn(x, y);
    __half2 h1 = __floats2half2_rn(z, w);
    uint2 u;
    u.x = *(unsigned*)&h0;
    u.y = *(unsigned*)&h1;
    return u;
}

__device__ __forceinline__ void add_half4(float4& a, uint2 u) {
    float2 lo = __half22float2(*(__half2*)&u.x);
    float2 hi = __half22float2(*(__half2*)&u.y);
    a.x += lo.x; a.y += lo.y; a.z += hi.x; a.w += hi.y;
}

// ---------------- weight pre-conversion (fp32 -> fp16, once per call) -------
__global__ void wcvt_k(const float* __restrict__ W1, const float* __restrict__ W2) {
    int i = blockIdx.x * blockDim.x + threadIdx.x;
    if (i < 128 * 128) g_w1h[i] = __float2half(W1[i]);
    if (i < 128 * 80) {
        int r = i / 80, n = i % 80;
        g_w2h[i] = __float2half((n < D_OUT) ? W2[(size_t)r * D_OUT + n] : 0.f);
    }
}

// ---------------- init: zero deg + scan flags, detect index width -----------
__global__ void init_k(const void* ei) {
    int i = blockIdx.x * blockDim.x + threadIdx.x;
    if (i < N_NODES) g_deg[i] = 0;
    if (i < 128) g_flag[i] = 0;
    if (i == 0) {
        const int* p = (const int*)ei;
        int is64 = 1;
        for (int t = 0; t < 1000; t++) {
            if (p[2 * t + 1] != 0) { is64 = 0; break; }
        }
        g_is64 = is64;
    }
}

__global__ void count_k(const void* __restrict__ ei) {
    int e = blockIdx.x * blockDim.x + threadIdx.x;
    if (e >= N_EDGES) return;
    int dst = load_idx(ei, (long long)N_EDGES + e, g_is64);
    atomicAdd(&g_deg[dst], 1);
}

// ---------------- fused scan: warp-shuffle + WARP-PARALLEL lookback ---------
__global__ void __launch_bounds__(1024) scan_k() {
    __shared__ int warp_sums[32];
    __shared__ int s_off;
    int t = threadIdx.x, b = blockIdx.x;
    int lane = t & 31, wid = t >> 5;
    int i = b * 1024 + t;
    int deg = (i < N_NODES) ? g_deg[i] : 0;

    int v = deg;
    #pragma unroll
    for (int off = 1; off < 32; off <<= 1) {
        int n = __shfl_up_sync(0xffffffffu, v, off);
        if (lane >= off) v += n;
    }
    if (lane == 31) warp_sums[wid] = v;
    __syncthreads();

    if (wid == 0) {
        int wv = warp_sums[lane];
        #pragma unroll
        for (int off = 1; off < 32; off <<= 1) {
            int n = __shfl_up_sync(0xffffffffu, wv, off);
            if (lane >= off) wv += n;
        }
        warp_sums[lane] = wv;
        int agg = __shfl_sync(0xffffffffu, wv, 31);   // block aggregate
        if (lane == 0) {
            *(volatile int*)&g_pval[b] = agg;
            __threadfence();
            *(volatile int*)&g_flag[b] = 1;
        }
        // warp-parallel lookback: inspect 32 predecessors per window
        int off = 0;
        int pbase = b - 1;
        while (pbase >= 0) {
            int p = pbase - lane;
            int f = 0;
            if (p >= 0) {
                do { f = *(volatile int*)&g_flag[p]; } while (f == 0);
            }
            __threadfence();
            int val = 0;
            if (p >= 0)
                val = (f == 2) ? *(volatile int*)&g_ival[p]
                               : *(volatile int*)&g_pval[p];
            unsigned done = __ballot_sync(0xffffffffu, p >= 0 && f == 2);
            int contrib;
            if (done) {
                int L = __ffs(done) - 1;   // nearest predecessor with inclusive prefix
                contrib = (lane < L) ? val : (lane == L ? val : 0);
            } else {
                contrib = val;
            }
            #pragma unroll
            for (int o = 16; o > 0; o >>= 1)
                contrib += __shfl_down_sync(0xffffffffu, contrib, o);
            contrib = __shfl_sync(0xffffffffu, contrib, 0);
            off += contrib;
            if (done) break;
            pbase -= 32;
        }
        if (lane == 0) {
            *(volatile int*)&g_ival[b] = off + agg;
            __threadfence();
            *(volatile int*)&g_flag[b] = 2;
            s_off = off;
        }
    }
    __syncthreads();

    int incl = v + (wid ? warp_sums[wid - 1] : 0) + s_off;
    if (i < N_NODES) {
        g_rowptr[i + 1] = incl;
        g_cursor[i] = incl - deg;
        g_dinv[i] = rsqrtf((float)(deg + 1));   // +1 self-loop
    }
    if (i == 0) g_rowptr[0] = 0;
}

__global__ void fill_k(const void* __restrict__ ei) {
    int e = blockIdx.x * blockDim.x + threadIdx.x;
    if (e >= N_EDGES) return;
    int is64 = g_is64;
    int src = load_idx(ei, e, is64);
    int dst = load_idx(ei, (long long)N_EDGES + e, is64);
    int pos = atomicAdd(&g_cursor[dst], 1);
    g_nbr[pos] = src;
}

// ---------------- GEMM 1 (fp16 HMMA): y1 = dinv .* (x @ W1), 128x128 --------
#define LDAH 136   // half stride for A/W smem tiles
#define LDC  132   // float stride for epilogue smem
__global__ void __launch_bounds__(256) gemm1_k(const float* __restrict__ A) {
    extern __shared__ char smraw[];
    __half* sA = (__half*)smraw;            // 64 x LDAH
    __half* sW = sA + 64 * LDAH;            // 128 x LDAH
    float*  sC = (float*)smraw;             // 64 x LDC (epilogue alias)
    int tid = threadIdx.x;
    int wid = tid >> 5;
    int wm = wid & 1, wn = wid >> 1;        // 2 x 4 warp grid
    int r0 = blockIdx.x * 64;

    #pragma unroll
    for (int i = 0; i < 8; i++) {
        int l = tid + i * 256;
        int row = l >> 5, q = l & 31;
        float4 v = make_float4(0.f, 0.f, 0.f, 0.f);
        int gr = r0 + row;
        if (gr < N_NODES) v = *(const float4*)(A + (size_t)gr * 128 + q * 4);
        *(uint2*)(sA + row * LDAH + q * 4) = pack_half4(v.x, v.y, v.z, v.w);
    }
    #pragma unroll
    for (int i = 0; i < 8; i++) {
        int l = tid + i * 256;
        int row = l >> 4, q = l & 15;
        *(uint4*)(sW + row * LDAH + q * 8) = *(const uint4*)(g_w1h + row * 128 + q * 8);
    }
    __syncthreads();

    wmma::fragment<wmma::accumulator, 16, 16, 16, float> acc[2][2];
    #pragma unroll
    for (int i = 0; i < 2; i++)
        #pragma unroll
        for (int j = 0; j < 2; j++)
            wmma::fill_fragment(acc[i][j], 0.f);

    #pragma unroll
    for (int k0 = 0; k0 < 128; k0 += 16) {
        wmma::fragment<wmma::matrix_a, 16, 16, 16, __half, wmma::row_major> af[2];
        wmma::fragment<wmma::matrix_b, 16, 16, 16, __half, wmma::row_major> bf[2];
        #pragma unroll
        for (int i = 0; i < 2; i++)
            wmma::load_matrix_sync(af[i], sA + (wm * 32 + i * 16) * LDAH + k0, LDAH);
        #pragma unroll
        for (int j = 0; j < 2; j++)
            wmma::load_matrix_sync(bf[j], sW + k0 * LDAH + wn * 32 + j * 16, LDAH);
        #pragma unroll
        for (int i = 0; i < 2; i++)
            #pragma unroll
            for (int j = 0; j < 2; j++)
                wmma::mma_sync(acc[i][j], af[i], bf[j], acc[i][j]);
    }

    __syncthreads();
    #pragma unroll
    for (int i = 0; i < 2; i++)
        #pragma unroll
        for (int j = 0; j < 2; j++)
            wmma::store_matrix_sync(sC + (wm * 32 + i * 16) * LDC + wn * 32 + j * 16,
                                    acc[i][j], LDC, wmma::mem_row_major);
    __syncthreads();
    #pragma unroll
    for (int i = 0; i < 8; i++) {
        int l = tid + i * 256;
        int row = l >> 5, q = l & 31;
        int gr = r0 + row;
        if (gr >= N_NODES) continue;
        float s = g_dinv[gr];
        float4 v = *(float4*)(sC + row * LDC + q * 4);
        *(uint2*)(g_y1 + (size_t)gr * 128 + q * 4) =
            pack_half4(v.x * s, v.y * s, v.z * s, v.w * s);
    }
}

// ---------------- GEMM 2 (fp16 HMMA): y2 = dinv .* (h @ W2), 128x70 ---------
#define LDW2H 88   // half stride for W2 smem
#define LDC2  84   // float stride for epilogue smem
__global__ void __launch_bounds__(320) gemm2_k() {
    extern __shared__ char smraw[];
    __half* sH = (__half*)smraw;            // 64 x LDAH
    __half* sW = sH + 64 * LDAH;            // 128 x LDW2H
    float*  sC = (float*)smraw;             // 64 x LDC2 (epilogue alias)
    int tid = threadIdx.x;
    int wid = tid >> 5;
    int wm = wid & 1, wn = wid >> 1;        // 2 x 5 warp grid
    int r0 = blockIdx.x * 64;

    for (int l = tid; l < 1024; l += 320) {
        int row = l >> 4, q = l & 15;
        int gr = r0 + row;
        uint4 u = make_uint4(0u, 0u, 0u, 0u);
        if (gr < N_NODES) u = *(const uint4*)(g_h + (size_t)gr * 128 + q * 8);
        *(uint4*)(sH + row * LDAH + q * 8) = u;
    }
    for (int l = tid; l < 1280; l += 320) {
        int row = l / 10, q = l % 10;
        *(uint4*)(sW + row * LDW2H + q * 8) = *(const uint4*)(g_w2h + row * 80 + q * 8);
    }
    __syncthreads();

    wmma::fragment<wmma::accumulator, 16, 16, 16, float> acc[2];
    wmma::fill_fragment(acc[0], 0.f);
    wmma::fill_fragment(acc[1], 0.f);

    #pragma unroll
    for (int k0 = 0; k0 < 128; k0 += 16) {
        wmma::fragment<wmma::matrix_a, 16, 16, 16, __half, wmma::row_major> af[2];
        wmma::fragment<wmma::matrix_b, 16, 16, 16, __half, wmma::row_major> bf;
        wmma::load_matrix_sync(af[0], sH + (wm * 32) * LDAH + k0, LDAH);
        wmma::load_matrix_sync(af[1], sH + (wm * 32 + 16) * LDAH + k0, LDAH);
        wmma::load_matrix_sync(bf, sW + k0 * LDW2H + wn * 16, LDW2H);
        wmma::mma_sync(acc[0], af[0], bf, acc[0]);
        wmma::mma_sync(acc[1], af[1], bf, acc[1]);
    }

    __syncthreads();
    wmma::store_matrix_sync(sC + (wm * 32) * LDC2 + wn * 16, acc[0], LDC2, wmma::mem_row_major);
    wmma::store_matrix_sync(sC + (wm * 32 + 16) * LDC2 + wn * 16, acc[1], LDC2, wmma::mem_row_major);
    __syncthreads();
    for (int l = tid; l < 64 * 18; l += 320) {
        int row = l / 18, q = l % 18;
        int gr = r0 + row;
        if (gr >= N_NODES) continue;
        float s = g_dinv[gr];
        float4 v = *(float4*)(sC + row * LDC2 + q * 4);
        *(uint2*)(g_y2 + (size_t)gr * D_OUT_P + q * 4) =
            pack_half4(v.x * s, v.y * s, v.z * s, v.w * s);
    }
}

// ---------------- gather 1: h = relu(dinv .* (Σ_nbr y1 + y1_self) + b1) -----
__global__ void __launch_bounds__(256) gather1_k(const float* __restrict__ b1) {
    int w = (blockIdx.x * 256 + threadIdx.x) >> 5;
    int lane = threadIdx.x & 31;
    if (w >= N_NODES) return;
    int start = g_rowptr[w], end = g_rowptr[w + 1];
    float4 a = make_float4(0.f, 0.f, 0.f, 0.f);
    add_half4(a, *(const uint2*)(g_y1 + (size_t)w * 128 + lane * 4));  // self
    for (int base = start; base < end; base += 32) {
        int idx = base + lane;
        int s = (idx < end) ? g_nbr[idx] : 0;
        int cnt = min(32, end - base);
        for (int j = 0; j < cnt; j++) {
            int sj = __shfl_sync(0xffffffffu, s, j);
            add_half4(a, *(const uint2*)(g_y1 + (size_t)sj * 128 + lane * 4));
        }
    }
    float d = g_dinv[w];
    float4 bb = *(const float4*)(b1 + lane * 4);
    float hx = fmaxf(0.f, fmaf(d, a.x, bb.x));
    float hy = fmaxf(0.f, fmaf(d, a.y, bb.y));
    float hz = fmaxf(0.f, fmaf(d, a.z, bb.z));
    float hw = fmaxf(0.f, fmaf(d, a.w, bb.w));
    *(uint2*)(g_h + (size_t)w * 128 + lane * 4) = pack_half4(hx, hy, hz, hw);
}

// ---------------- gather 2: out = dinv .* (Σ_nbr y2 + y2_self) + b2 ---------
__global__ void __launch_bounds__(256) gather2_k(const float* __restrict__ b2,
                                                 float* __restrict__ out) {
    int w = (blockIdx.x * 256 + threadIdx.x) >> 5;
    int lane = threadIdx.x & 31;
    if (w >= N_NODES) return;
    int start = g_rowptr[w], end = g_rowptr[w + 1];
    float4 a = make_float4(0.f, 0.f, 0.f, 0.f);
    bool act = lane < 18;
    size_t co = (size_t)lane * 4;
    if (act) add_half4(a, *(const uint2*)(g_y2 + (size_t)w * D_OUT_P + co));
    for (int base = start; base < end; base += 32) {
        int idx = base + lane;
        int s = (idx < end) ? g_nbr[idx] : 0;
        int cnt = min(32, end - base);
        for (int j = 0; j < cnt; j++) {
            int sj = __shfl_sync(0xffffffffu, s, j);
            if (act) add_half4(a, *(const uint2*)(g_y2 + (size_t)sj * D_OUT_P + co));
        }
    }
    if (act) {
        float d = g_dinv[w];
        int c = lane * 4;
        float* o = out + (size_t)w * D_OUT + c;
        float2 r0 = make_float2(fmaf(d, a.x, b2[c]), fmaf(d, a.y, b2[c + 1]));
        *(float2*)o = r0;
        if (lane < 17) {
            float2 r1 = make_float2(fmaf(d, a.z, b2[c + 2]), fmaf(d, a.w, b2[c + 3]));
            *(float2*)(o + 2) = r1;
        }
    }
}

// ---------------- launch -----------------------------------------------------
extern "C" void kernel_launch(void* const* d_in, const int* in_sizes, int n_in,
                              void* d_out, int out_size) {
    const float* x  = (const float*)d_in[0];
    const void*  ei = d_in[1];
    const float* W1 = (const float*)d_in[2];
    const float* b1 = (const float*)d_in[3];
    const float* W2 = (const float*)d_in[4];
    const float* b2 = (const float*)d_in[5];
    float* out = (float*)d_out;

    const int smem1 = (64 * LDAH + 128 * LDAH) * 2 > 64 * LDC * 4
                    ? (64 * LDAH + 128 * LDAH) * 2 : 64 * LDC * 4;     // 52224
    const int smem2 = (64 * LDAH + 128 * LDW2H) * 2 > 64 * LDC2 * 4
                    ? (64 * LDAH + 128 * LDW2H) * 2 : 64 * LDC2 * 4;   // 39936

    static cudaStream_t s2 = nullptr;
    static cudaEvent_t ev0 = nullptr, ev_fork = nullptr, ev_join = nullptr;
    if (!s2) {
        cudaStreamCreateWithFlags(&s2, cudaStreamNonBlocking);
        cudaEventCreateWithFlags(&ev0, cudaEventDisableTiming);
        cudaEventCreateWithFlags(&ev_fork, cudaEventDisableTiming);
        cudaEventCreateWithFlags(&ev_join, cudaEventDisableTiming);
        cudaFuncSetAttribute(gemm1_k, cudaFuncAttributeMaxDynamicSharedMemorySize, smem1);
        cudaFuncSetAttribute(gemm2_k, cudaFuncAttributeMaxDynamicSharedMemorySize, smem2);
    }

    // fork for weight conversion (no deps; overlaps the CSR chain)
    cudaEventRecord(ev0, 0);
    cudaStreamWaitEvent(s2, ev0, 0);
    wcvt_k<<<64, 256, 0, s2>>>(W1, W2);

    init_k<<<(N_NODES + 255) / 256, 256>>>(ei);
    count_k<<<(N_EDGES + 255) / 256, 256>>>(ei);
    scan_k<<<NSCAN, 1024>>>();

    // fork: gemm1 (needs dinv from scan + fp16 W1) runs concurrent with fill
    cudaEventRecord(ev_fork, 0);
    cudaStreamWaitEvent(s2, ev_fork, 0);
    gemm1_k<<<(N_NODES + 63) / 64, 256, smem1, s2>>>(x);
    fill_k<<<(N_EDGES + 255) / 256, 256>>>(ei);
    cudaEventRecord(ev_join, s2);
    cudaStreamWaitEvent(0, ev_join, 0);

    gather1_k<<<(N_NODES * 32 + 255) / 256, 256>>>(b1);
    gemm2_k<<<(N_NODES + 63) / 64, 320, smem2>>>();
    gather2_k<<<(N_NODES * 32 + 255) / 256, 256>>>(b2, out);
}

// round 15
// speedup vs baseline: 1.1759x; 1.0216x over previous
#include <cuda_runtime.h>
#include <cuda_fp16.h>
#include <mma.h>
#include <cstdint>

using namespace nvcuda;

#define N_NODES 100000
#define N_EDGES 1600000
#define D_IN    128
#define D_HID   128
#define D_OUT   70
#define D_OUT_P 72   // padded stride for layer-2 intermediates
#define NSCAN   ((N_NODES + 1023) / 1024)   // 98 scan blocks

// ---------------- scratch (static device memory; no allocation) -------------
__device__ __align__(256) int    g_deg   [N_NODES];
__device__ __align__(256) float  g_dinv  [N_NODES];
__device__ __align__(256) int    g_rowptr[N_NODES + 1];
__device__ __align__(256) int    g_cursor[N_NODES];
__device__ __align__(256) int    g_flag  [128];
__device__ __align__(256) int    g_pval  [128];
__device__ __align__(256) int    g_ival  [128];
__device__ __align__(256) int    g_nbr   [N_EDGES];
__device__ __align__(256) __half g_w1h   [128 * 128];   // W1 in fp16
__device__ __align__(256) __half g_w2h   [128 * 80];    // W2 in fp16, padded to 80
__device__ __align__(256) __half g_y1    [(size_t)N_NODES * D_HID];   // dinv-scaled x@W1
__device__ __align__(256) __half g_h     [(size_t)N_NODES * D_HID];
__device__ __align__(256) __half g_y2    [(size_t)N_NODES * D_OUT_P]; // dinv-scaled h@W2
__device__ int g_is64;

// ---------------- helpers ----------------------------------------------------
__device__ __forceinline__ int load_idx(const void* ei, long long i, int is64) {
    return is64 ? (int)(((const long long*)ei)[i]) : ((const int*)ei)[i];
}

__device__ __forceinline__ uint2 pack_half4(float x, float y, float z, float w) {
    __half2 h0 = __floats2half2_rn(x, y);
    __half2 h1 = __floats2half2_rn(z, w);
    uint2 u;
    u.x = *(unsigned*)&h0;
    u.y = *(unsigned*)&h1;
    return u;
}

__device__ __forceinline__ void add_half4(float4& a, uint2 u) {
    float2 lo = __half22float2(*(__half2*)&u.x);
    float2 hi = __half22float2(*(__half2*)&u.y);
    a.x += lo.x; a.y += lo.y; a.z += hi.x; a.w += hi.y;
}

// ---------------- weight pre-conversion (fp32 -> fp16, once per call) -------
__global__ void wcvt_k(const float* __restrict__ W1, const float* __restrict__ W2) {
    int i = blockIdx.x * blockDim.x + threadIdx.x;
    if (i < 128 * 128) g_w1h[i] = __float2half(W1[i]);
    if (i < 128 * 80) {
        int r = i / 80, n = i % 80;
        g_w2h[i] = __float2half((n < D_OUT) ? W2[(size_t)r * D_OUT + n] : 0.f);
    }
}

// ---------------- init: zero deg + scan flags, detect index width -----------
__global__ void init_k(const void* ei) {
    int i = blockIdx.x * blockDim.x + threadIdx.x;
    if (i < N_NODES) g_deg[i] = 0;
    if (i < 128) g_flag[i] = 0;
    if (i == 0) {
        const int* p = (const int*)ei;
        int is64 = 1;
        for (int t = 0; t < 1000; t++) {
            if (p[2 * t + 1] != 0) { is64 = 0; break; }
        }
        g_is64 = is64;
    }
}

__global__ void count_k(const void* __restrict__ ei) {
    int e = blockIdx.x * blockDim.x + threadIdx.x;
    if (e >= N_EDGES) return;
    int dst = load_idx(ei, (long long)N_EDGES + e, g_is64);
    atomicAdd(&g_deg[dst], 1);
}

// ---------------- fused scan: warp-shuffle + WARP-PARALLEL lookback ---------
__global__ void __launch_bounds__(1024) scan_k() {
    __shared__ int warp_sums[32];
    __shared__ int s_off;
    int t = threadIdx.x, b = blockIdx.x;
    int lane = t & 31, wid = t >> 5;
    int i = b * 1024 + t;
    int deg = (i < N_NODES) ? g_deg[i] : 0;

    int v = deg;
    #pragma unroll
    for (int off = 1; off < 32; off <<= 1) {
        int n = __shfl_up_sync(0xffffffffu, v, off);
        if (lane >= off) v += n;
    }
    if (lane == 31) warp_sums[wid] = v;
    __syncthreads();

    if (wid == 0) {
        int wv = warp_sums[lane];
        #pragma unroll
        for (int off = 1; off < 32; off <<= 1) {
            int n = __shfl_up_sync(0xffffffffu, wv, off);
            if (lane >= off) wv += n;
        }
        warp_sums[lane] = wv;
        int agg = __shfl_sync(0xffffffffu, wv, 31);   // block aggregate
        if (lane == 0) {
            *(volatile int*)&g_pval[b] = agg;
            __threadfence();
            *(volatile int*)&g_flag[b] = 1;
        }
        // warp-parallel lookback: inspect 32 predecessors per window
        int off = 0;
        int pbase = b - 1;
        while (pbase >= 0) {
            int p = pbase - lane;
            int f = 0;
            if (p >= 0) {
                do { f = *(volatile int*)&g_flag[p]; } while (f == 0);
            }
            __threadfence();
            int val = 0;
            if (p >= 0)
                val = (f == 2) ? *(volatile int*)&g_ival[p]
                               : *(volatile int*)&g_pval[p];
            unsigned done = __ballot_sync(0xffffffffu, p >= 0 && f == 2);
            int contrib;
            if (done) {
                int L = __ffs(done) - 1;   // nearest predecessor with inclusive prefix
                contrib = (lane < L) ? val : (lane == L ? val : 0);
            } else {
                contrib = val;
            }
            #pragma unroll
            for (int o = 16; o > 0; o >>= 1)
                contrib += __shfl_down_sync(0xffffffffu, contrib, o);
            contrib = __shfl_sync(0xffffffffu, contrib, 0);
            off += contrib;
            if (done) break;
            pbase -= 32;
        }
        if (lane == 0) {
            *(volatile int*)&g_ival[b] = off + agg;
            __threadfence();
            *(volatile int*)&g_flag[b] = 2;
            s_off = off;
        }
    }
    __syncthreads();

    int incl = v + (wid ? warp_sums[wid - 1] : 0) + s_off;
    if (i < N_NODES) {
        g_rowptr[i + 1] = incl;
        g_cursor[i] = incl - deg;
        g_dinv[i] = rsqrtf((float)(deg + 1));   // +1 self-loop
    }
    if (i == 0) g_rowptr[0] = 0;
}

__global__ void fill_k(const void* __restrict__ ei) {
    int e = blockIdx.x * blockDim.x + threadIdx.x;
    if (e >= N_EDGES) return;
    int is64 = g_is64;
    int src = load_idx(ei, e, is64);
    int dst = load_idx(ei, (long long)N_EDGES + e, is64);
    int pos = atomicAdd(&g_cursor[dst], 1);
    g_nbr[pos] = src;
}

// ---------------- GEMM 1 (fp16 HMMA): y1 = dinv .* (x @ W1), 128x128 --------
#define LDAH 136   // half stride for A/W smem tiles
#define LDC  132   // float stride for epilogue smem
__global__ void __launch_bounds__(256) gemm1_k(const float* __restrict__ A) {
    extern __shared__ char smraw[];
    __half* sA = (__half*)smraw;            // 64 x LDAH
    __half* sW = sA + 64 * LDAH;            // 128 x LDAH
    float*  sC = (float*)smraw;             // 64 x LDC (epilogue alias)
    int tid = threadIdx.x;
    int wid = tid >> 5;
    int wm = wid & 1, wn = wid >> 1;        // 2 x 4 warp grid
    int r0 = blockIdx.x * 64;

    #pragma unroll
    for (int i = 0; i < 8; i++) {
        int l = tid + i * 256;
        int row = l >> 5, q = l & 31;
        float4 v = make_float4(0.f, 0.f, 0.f, 0.f);
        int gr = r0 + row;
        if (gr < N_NODES) v = *(const float4*)(A + (size_t)gr * 128 + q * 4);
        *(uint2*)(sA + row * LDAH + q * 4) = pack_half4(v.x, v.y, v.z, v.w);
    }
    #pragma unroll
    for (int i = 0; i < 8; i++) {
        int l = tid + i * 256;
        int row = l >> 4, q = l & 15;
        *(uint4*)(sW + row * LDAH + q * 8) = *(const uint4*)(g_w1h + row * 128 + q * 8);
    }
    __syncthreads();

    wmma::fragment<wmma::accumulator, 16, 16, 16, float> acc[2][2];
    #pragma unroll
    for (int i = 0; i < 2; i++)
        #pragma unroll
        for (int j = 0; j < 2; j++)
            wmma::fill_fragment(acc[i][j], 0.f);

    #pragma unroll
    for (int k0 = 0; k0 < 128; k0 += 16) {
        wmma::fragment<wmma::matrix_a, 16, 16, 16, __half, wmma::row_major> af[2];
        wmma::fragment<wmma::matrix_b, 16, 16, 16, __half, wmma::row_major> bf[2];
        #pragma unroll
        for (int i = 0; i < 2; i++)
            wmma::load_matrix_sync(af[i], sA + (wm * 32 + i * 16) * LDAH + k0, LDAH);
        #pragma unroll
        for (int j = 0; j < 2; j++)
            wmma::load_matrix_sync(bf[j], sW + k0 * LDAH + wn * 32 + j * 16, LDAH);
        #pragma unroll
        for (int i = 0; i < 2; i++)
            #pragma unroll
            for (int j = 0; j < 2; j++)
                wmma::mma_sync(acc[i][j], af[i], bf[j], acc[i][j]);
    }

    __syncthreads();
    #pragma unroll
    for (int i = 0; i < 2; i++)
        #pragma unroll
        for (int j = 0; j < 2; j++)
            wmma::store_matrix_sync(sC + (wm * 32 + i * 16) * LDC + wn * 32 + j * 16,
                                    acc[i][j], LDC, wmma::mem_row_major);
    __syncthreads();
    #pragma unroll
    for (int i = 0; i < 8; i++) {
        int l = tid + i * 256;
        int row = l >> 5, q = l & 31;
        int gr = r0 + row;
        if (gr >= N_NODES) continue;
        float s = g_dinv[gr];
        float4 v = *(float4*)(sC + row * LDC + q * 4);
        *(uint2*)(g_y1 + (size_t)gr * 128 + q * 4) =
            pack_half4(v.x * s, v.y * s, v.z * s, v.w * s);
    }
}

// ---------------- GEMM 2 (fp16 HMMA): y2 = dinv .* (h @ W2), 128x70 ---------
#define LDW2H 88   // half stride for W2 smem
#define LDC2  84   // float stride for epilogue smem
__global__ void __launch_bounds__(320) gemm2_k() {
    extern __shared__ char smraw[];
    __half* sH = (__half*)smraw;            // 64 x LDAH
    __half* sW = sH + 64 * LDAH;            // 128 x LDW2H
    float*  sC = (float*)smraw;             // 64 x LDC2 (epilogue alias)
    int tid = threadIdx.x;
    int wid = tid >> 5;
    int wm = wid & 1, wn = wid >> 1;        // 2 x 5 warp grid
    int r0 = blockIdx.x * 64;

    for (int l = tid; l < 1024; l += 320) {
        int row = l >> 4, q = l & 15;
        int gr = r0 + row;
        uint4 u = make_uint4(0u, 0u, 0u, 0u);
        if (gr < N_NODES) u = *(const uint4*)(g_h + (size_t)gr * 128 + q * 8);
        *(uint4*)(sH + row * LDAH + q * 8) = u;
    }
    for (int l = tid; l < 1280; l += 320) {
        int row = l / 10, q = l % 10;
        *(uint4*)(sW + row * LDW2H + q * 8) = *(const uint4*)(g_w2h + row * 80 + q * 8);
    }
    __syncthreads();

    wmma::fragment<wmma::accumulator, 16, 16, 16, float> acc[2];
    wmma::fill_fragment(acc[0], 0.f);
    wmma::fill_fragment(acc[1], 0.f);

    #pragma unroll
    for (int k0 = 0; k0 < 128; k0 += 16) {
        wmma::fragment<wmma::matrix_a, 16, 16, 16, __half, wmma::row_major> af[2];
        wmma::fragment<wmma::matrix_b, 16, 16, 16, __half, wmma::row_major> bf;
        wmma::load_matrix_sync(af[0], sH + (wm * 32) * LDAH + k0, LDAH);
        wmma::load_matrix_sync(af[1], sH + (wm * 32 + 16) * LDAH + k0, LDAH);
        wmma::load_matrix_sync(bf, sW + k0 * LDW2H + wn * 16, LDW2H);
        wmma::mma_sync(acc[0], af[0], bf, acc[0]);
        wmma::mma_sync(acc[1], af[1], bf, acc[1]);
    }

    __syncthreads();
    wmma::store_matrix_sync(sC + (wm * 32) * LDC2 + wn * 16, acc[0], LDC2, wmma::mem_row_major);
    wmma::store_matrix_sync(sC + (wm * 32 + 16) * LDC2 + wn * 16, acc[1], LDC2, wmma::mem_row_major);
    __syncthreads();
    for (int l = tid; l < 64 * 18; l += 320) {
        int row = l / 18, q = l % 18;
        int gr = r0 + row;
        if (gr >= N_NODES) continue;
        float s = g_dinv[gr];
        float4 v = *(float4*)(sC + row * LDC2 + q * 4);
        *(uint2*)(g_y2 + (size_t)gr * D_OUT_P + q * 4) =
            pack_half4(v.x * s, v.y * s, v.z * s, v.w * s);
    }
}

// ---------------- gather 1: h = relu(dinv .* (Σ_nbr y1 + y1_self) + b1) -----
// one warp per node; lane l owns columns [4l, 4l+4); shfl index broadcast;
// j-loop unrolled x2 with dual accumulators (same access pattern, more MLP)
__global__ void __launch_bounds__(256) gather1_k(const float* __restrict__ b1) {
    int w = (blockIdx.x * 256 + threadIdx.x) >> 5;
    int lane = threadIdx.x & 31;
    if (w >= N_NODES) return;
    int start = g_rowptr[w], end = g_rowptr[w + 1];
    float4 a = make_float4(0.f, 0.f, 0.f, 0.f);
    float4 a2 = make_float4(0.f, 0.f, 0.f, 0.f);
    add_half4(a, *(const uint2*)(g_y1 + (size_t)w * 128 + lane * 4));  // self
    for (int base = start; base < end; base += 32) {
        int idx = base + lane;
        int s = (idx < end) ? g_nbr[idx] : 0;
        int cnt = min(32, end - base);
        int j = 0;
        for (; j + 1 < cnt; j += 2) {
            int sj0 = __shfl_sync(0xffffffffu, s, j);
            int sj1 = __shfl_sync(0xffffffffu, s, j + 1);
            uint2 u0 = *(const uint2*)(g_y1 + (size_t)sj0 * 128 + lane * 4);
            uint2 u1 = *(const uint2*)(g_y1 + (size_t)sj1 * 128 + lane * 4);
            add_half4(a, u0);
            add_half4(a2, u1);
        }
        if (j < cnt) {
            int sj = __shfl_sync(0xffffffffu, s, j);
            add_half4(a, *(const uint2*)(g_y1 + (size_t)sj * 128 + lane * 4));
        }
    }
    a.x += a2.x; a.y += a2.y; a.z += a2.z; a.w += a2.w;
    float d = g_dinv[w];
    float4 bb = *(const float4*)(b1 + lane * 4);
    float hx = fmaxf(0.f, fmaf(d, a.x, bb.x));
    float hy = fmaxf(0.f, fmaf(d, a.y, bb.y));
    float hz = fmaxf(0.f, fmaf(d, a.z, bb.z));
    float hw = fmaxf(0.f, fmaf(d, a.w, bb.w));
    *(uint2*)(g_h + (size_t)w * 128 + lane * 4) = pack_half4(hx, hy, hz, hw);
}

// ---------------- gather 2: out = dinv .* (Σ_nbr y2 + y2_self) + b2 ---------
__global__ void __launch_bounds__(256) gather2_k(const float* __restrict__ b2,
                                                 float* __restrict__ out) {
    int w = (blockIdx.x * 256 + threadIdx.x) >> 5;
    int lane = threadIdx.x & 31;
    if (w >= N_NODES) return;
    int start = g_rowptr[w], end = g_rowptr[w + 1];
    float4 a = make_float4(0.f, 0.f, 0.f, 0.f);
    float4 a2 = make_float4(0.f, 0.f, 0.f, 0.f);
    bool act = lane < 18;
    size_t co = (size_t)lane * 4;
    if (act) add_half4(a, *(const uint2*)(g_y2 + (size_t)w * D_OUT_P + co));
    for (int base = start; base < end; base += 32) {
        int idx = base + lane;
        int s = (idx < end) ? g_nbr[idx] : 0;
        int cnt = min(32, end - base);
        int j = 0;
        for (; j + 1 < cnt; j += 2) {
            int sj0 = __shfl_sync(0xffffffffu, s, j);
            int sj1 = __shfl_sync(0xffffffffu, s, j + 1);
            if (act) {
                uint2 u0 = *(const uint2*)(g_y2 + (size_t)sj0 * D_OUT_P + co);
                uint2 u1 = *(const uint2*)(g_y2 + (size_t)sj1 * D_OUT_P + co);
                add_half4(a, u0);
                add_half4(a2, u1);
            }
        }
        if (j < cnt) {
            int sj = __shfl_sync(0xffffffffu, s, j);
            if (act) add_half4(a, *(const uint2*)(g_y2 + (size_t)sj * D_OUT_P + co));
        }
    }
    if (act) {
        a.x += a2.x; a.y += a2.y; a.z += a2.z; a.w += a2.w;
        float d = g_dinv[w];
        int c = lane * 4;
        float* o = out + (size_t)w * D_OUT + c;
        float2 r0 = make_float2(fmaf(d, a.x, b2[c]), fmaf(d, a.y, b2[c + 1]));
        *(float2*)o = r0;
        if (lane < 17) {
            float2 r1 = make_float2(fmaf(d, a.z, b2[c + 2]), fmaf(d, a.w, b2[c + 3]));
            *(float2*)(o + 2) = r1;
        }
    }
}

// ---------------- launch -----------------------------------------------------
extern "C" void kernel_launch(void* const* d_in, const int* in_sizes, int n_in,
                              void* d_out, int out_size) {
    const float* x  = (const float*)d_in[0];
    const void*  ei = d_in[1];
    const float* W1 = (const float*)d_in[2];
    const float* b1 = (const float*)d_in[3];
    const float* W2 = (const float*)d_in[4];
    const float* b2 = (const float*)d_in[5];
    float* out = (float*)d_out;

    const int smem1 = (64 * LDAH + 128 * LDAH) * 2 > 64 * LDC * 4
                    ? (64 * LDAH + 128 * LDAH) * 2 : 64 * LDC * 4;     // 52224
    const int smem2 = (64 * LDAH + 128 * LDW2H) * 2 > 64 * LDC2 * 4
                    ? (64 * LDAH + 128 * LDW2H) * 2 : 64 * LDC2 * 4;   // 39936

    static cudaStream_t s2 = nullptr;
    static cudaEvent_t ev0 = nullptr, ev_fork = nullptr, ev_join = nullptr;
    if (!s2) {
        cudaStreamCreateWithFlags(&s2, cudaStreamNonBlocking);
        cudaEventCreateWithFlags(&ev0, cudaEventDisableTiming);
        cudaEventCreateWithFlags(&ev_fork, cudaEventDisableTiming);
        cudaEventCreateWithFlags(&ev_join, cudaEventDisableTiming);
        cudaFuncSetAttribute(gemm1_k, cudaFuncAttributeMaxDynamicSharedMemorySize, smem1);
        cudaFuncSetAttribute(gemm2_k, cudaFuncAttributeMaxDynamicSharedMemorySize, smem2);
    }

    // fork for weight conversion (no deps; overlaps the CSR chain)
    cudaEventRecord(ev0, 0);
    cudaStreamWaitEvent(s2, ev0, 0);
    wcvt_k<<<64, 256, 0, s2>>>(W1, W2);

    init_k<<<(N_NODES + 255) / 256, 256>>>(ei);
    count_k<<<(N_EDGES + 255) / 256, 256>>>(ei);
    scan_k<<<NSCAN, 1024>>>();

    // fork: gemm1 (needs dinv from scan + fp16 W1) runs concurrent with fill
    cudaEventRecord(ev_fork, 0);
    cudaStreamWaitEvent(s2, ev_fork, 0);
    gemm1_k<<<(N_NODES + 63) / 64, 256, smem1, s2>>>(x);
    fill_k<<<(N_EDGES + 255) / 256, 256>>>(ei);
    cudaEventRecord(ev_join, s2);
    cudaStreamWaitEvent(0, ev_join, 0);

    gather1_k<<<(N_NODES * 32 + 255) / 256, 256>>>(b1);
    gemm2_k<<<(N_NODES + 63) / 64, 320, smem2>>>();
    gather2_k<<<(N_NODES * 32 + 255) / 256, 256>>>(b2, out);
}